// round 1
// baseline (speedup 1.0000x reference)
#include <cuda_runtime.h>
#include <cuda_bf16.h>
#include <cstdint>

#define D      256
#define MAXN   8192
#define BR     64      // rows per CTA (kernel 2)
#define BC     128     // cols per tile (kernel 2)
#define SROW   264     // padded smem row stride (bf16 elems): 528B -> conflict-free
#define LOG2E_OVER_T 28.853900817779268f   // log2(e)/0.05
#define INV_T        20.0f

// ---------------- scratch (static device globals; no allocations) ----------
__device__ __nv_bfloat16 g_a[MAXN * D];   // normalized A, scaled by log2(e)/T
__device__ __nv_bfloat16 g_b[MAXN * D];   // normalized B
__device__ float         g_diag[MAXN];    // exact fp32 diagonal logits (natural units)
__device__ float         g_rowt[MAXN];    // per-row LSE - diag

// ---------------- helpers --------------------------------------------------
__device__ __forceinline__ float exp2f_fast(float f) {
    // valid for |f| < ~2^20; here |f| <= ~29. Pure fma/alu pipe, no MUFU.
    float fr = f + 12582912.0f;                 // 1.5*2^23 magic: round-to-nearest int
    int   n  = __float_as_int(fr);              // low bits hold the integer
    float fl = fr - 12582912.0f;
    float t  = f - fl;                          // t in [-0.5, 0.5]
    float p  = 1.3333558146e-3f;                // deg-5 Taylor of 2^t (rel err ~4e-6)
    p = fmaf(p, t, 9.6181291076e-3f);
    p = fmaf(p, t, 5.5504108665e-2f);
    p = fmaf(p, t, 2.4022650696e-1f);
    p = fmaf(p, t, 6.9314718056e-1f);
    p = fmaf(p, t, 1.0f);
    float sc = __int_as_float((n << 23) + 0x3f800000); // 2^round(f)
    return p * sc;
}

__device__ __forceinline__ void cp_async16(void* smem_dst, const void* gsrc) {
    uint32_t s = (uint32_t)__cvta_generic_to_shared(smem_dst);
    asm volatile("cp.async.cg.shared.global [%0], [%1], 16;\n" :: "r"(s), "l"(gsrc));
}
#define CP_COMMIT() asm volatile("cp.async.commit_group;\n" ::: "memory")
#define CP_WAIT1()  asm volatile("cp.async.wait_group 1;\n" ::: "memory")

__device__ __forceinline__ void mma_bf16(float c[4], uint32_t a0, uint32_t a1,
                                         uint32_t a2, uint32_t a3,
                                         uint32_t b0, uint32_t b1) {
    asm volatile(
        "mma.sync.aligned.m16n8k16.row.col.f32.bf16.bf16.f32 "
        "{%0,%1,%2,%3}, {%4,%5,%6,%7}, {%8,%9}, {%0,%1,%2,%3};\n"
        : "+f"(c[0]), "+f"(c[1]), "+f"(c[2]), "+f"(c[3])
        : "r"(a0), "r"(a1), "r"(a2), "r"(a3), "r"(b0), "r"(b1));
}

// ---------------- kernel 1: norms + exact diagonal -------------------------
__global__ void norm_kernel(const float* __restrict__ a, const float* __restrict__ b) {
    int row  = blockIdx.x;
    int t    = threadIdx.x;             // 256 threads = D
    float av = a[row * D + t];
    float bv = b[row * D + t];
    float sa = av * av, sb = bv * bv, sd = av * bv;
    #pragma unroll
    for (int o = 16; o; o >>= 1) {
        sa += __shfl_xor_sync(0xffffffffu, sa, o);
        sb += __shfl_xor_sync(0xffffffffu, sb, o);
        sd += __shfl_xor_sync(0xffffffffu, sd, o);
    }
    __shared__ float red[3][8];
    __shared__ float bc[2];
    int w = t >> 5, lane = t & 31;
    if (lane == 0) { red[0][w] = sa; red[1][w] = sb; red[2][w] = sd; }
    __syncthreads();
    if (t == 0) {
        float A = 0.f, B = 0.f, Dd = 0.f;
        #pragma unroll
        for (int i = 0; i < 8; i++) { A += red[0][i]; B += red[1][i]; Dd += red[2][i]; }
        float ia = 1.f / fmaxf(sqrtf(A), 1e-8f);
        float ib = 1.f / fmaxf(sqrtf(B), 1e-8f);
        bc[0] = ia; bc[1] = ib;
        g_diag[row] = Dd * ia * ib * INV_T;       // exact fp32 diagonal, natural units
    }
    __syncthreads();
    float ia = bc[0], ib = bc[1];
    g_a[row * D + t] = __float2bfloat16(av * ia * LOG2E_OVER_T);
    g_b[row * D + t] = __float2bfloat16(bv * ib);
}

// ---------------- kernel 2: fused GEMM + exp2 + row-sum --------------------
// grid = N/BR CTAs, 256 threads (8 warps). Warp tile = 16 rows x 64 cols.
// A tile (64x256 bf16) resident; B tiles (128x256 bf16) double-buffered via cp.async.
__global__ __launch_bounds__(256, 1) void sim_lse_kernel(int N) {
    extern __shared__ __nv_bfloat16 sm[];
    __nv_bfloat16* As = sm;                              // BR*SROW
    __nv_bfloat16* Bs = sm + BR * SROW;                  // 2 * BC*SROW
    float* partial = (float*)(sm + BR * SROW + 2 * BC * SROW); // [2][BR]

    int tid  = threadIdx.x;
    int w    = tid >> 5, lane = tid & 31;
    int wr   = (w & 3) << 4;     // warp row offset within CTA tile [0,64)
    int wc   = (w >> 2) << 6;    // warp col offset within col tile [0,128)
    int rowBase = blockIdx.x * BR;

    // load A tile (plain loads; 64 rows x 32 uint4)
    for (int i = tid; i < BR * 32; i += 256) {
        int r = i >> 5, c = i & 31;
        *(uint4*)(As + r * SROW + c * 8) =
            *(const uint4*)(g_a + (rowBase + r) * D + c * 8);
    }
    // prologue: B tile 0 via cp.async
    for (int i = tid; i < BC * 32; i += 256) {
        int r = i >> 5, c = i & 31;
        cp_async16(Bs + r * SROW + c * 8, g_b + r * D + c * 8);
    }
    CP_COMMIT();

    const int NT = N / BC;
    float rs0 = 0.f, rs1 = 0.f;   // running sum-of-exp for rows (lane/4), (lane/4 + 8)

    int arow  = wr + (lane >> 2);
    int klane = (lane & 3) << 1;

    for (int ct = 0; ct < NT; ct++) {
        __syncthreads();   // prior compute done before overwriting buffer (ct+1)&1
        __nv_bfloat16* Bcur = Bs + (ct & 1) * (BC * SROW);
        if (ct + 1 < NT) {
            __nv_bfloat16* Bnext = Bs + ((ct + 1) & 1) * (BC * SROW);
            const __nv_bfloat16* src = g_b + (size_t)(ct + 1) * BC * D;
            for (int i = tid; i < BC * 32; i += 256) {
                int r = i >> 5, c = i & 31;
                cp_async16(Bnext + r * SROW + c * 8, src + r * D + c * 8);
            }
        }
        CP_COMMIT();       // (possibly empty group on last iter — keeps wait_group 1 valid)
        CP_WAIT1();        // groups retire in order: tile ct is complete
        __syncthreads();

        float acc[8][4];
        #pragma unroll
        for (int nt = 0; nt < 8; nt++) {
            acc[nt][0] = acc[nt][1] = acc[nt][2] = acc[nt][3] = 0.f;
        }

        #pragma unroll
        for (int k = 0; k < D; k += 16) {
            uint32_t a0 = *(const uint32_t*)(As + arow * SROW + k + klane);
            uint32_t a1 = *(const uint32_t*)(As + (arow + 8) * SROW + k + klane);
            uint32_t a2 = *(const uint32_t*)(As + arow * SROW + k + klane + 8);
            uint32_t a3 = *(const uint32_t*)(As + (arow + 8) * SROW + k + klane + 8);
            #pragma unroll
            for (int nt = 0; nt < 8; nt++) {
                const __nv_bfloat16* bp =
                    Bcur + (wc + nt * 8 + (lane >> 2)) * SROW + k + klane;
                uint32_t b0 = *(const uint32_t*)(bp);
                uint32_t b1 = *(const uint32_t*)(bp + 8);
                mma_bf16(acc[nt], a0, a1, a2, a3, b0, b1);
            }
        }
        // logits are in log2 units (scale folded into A); plain running Sum-exp,
        // no max needed since |logit| <= 20 nats -> exp in [2e-9, 5e8].
        #pragma unroll
        for (int nt = 0; nt < 8; nt++) {
            rs0 += exp2f_fast(acc[nt][0]) + exp2f_fast(acc[nt][1]);
            rs1 += exp2f_fast(acc[nt][2]) + exp2f_fast(acc[nt][3]);
        }
    }

    // reduce the 4 lanes sharing each row (cols split across lane%4)
    rs0 += __shfl_xor_sync(0xffffffffu, rs0, 1);
    rs0 += __shfl_xor_sync(0xffffffffu, rs0, 2);
    rs1 += __shfl_xor_sync(0xffffffffu, rs1, 1);
    rs1 += __shfl_xor_sync(0xffffffffu, rs1, 2);
    if ((lane & 3) == 0) {
        int r = wr + (lane >> 2);
        partial[(w >> 2) * BR + r]     = rs0;
        partial[(w >> 2) * BR + r + 8] = rs1;
    }
    __syncthreads();
    if (tid < BR) {
        float s  = partial[tid] + partial[BR + tid];     // combine the two col-half warps
        int   gr = rowBase + tid;
        g_rowt[gr] = logf(s) - g_diag[gr];               // LSE_i - s_ii (natural units)
    }
}

// ---------------- kernel 3: mean reduction ---------------------------------
__global__ void reduce_kernel(float* __restrict__ out, int N) {
    __shared__ float s[256];
    int t = threadIdx.x;
    float acc = 0.f;
    for (int i = t; i < N; i += 256) acc += g_rowt[i];
    s[t] = acc;
    __syncthreads();
    for (int o = 128; o; o >>= 1) {
        if (t < o) s[t] += s[t + o];
        __syncthreads();
    }
    if (t == 0) out[0] = s[0] / (float)N;
}

// ---------------- launch ---------------------------------------------------
extern "C" void kernel_launch(void* const* d_in, const int* in_sizes, int n_in,
                              void* d_out, int out_size) {
    const float* a = (const float*)d_in[0];   // text_embeddings      [N, 256]
    const float* b = (const float*)d_in[1];   // text_pos_embeddings  [N, 256]
    int N = in_sizes[0] / D;                  // 8192
    if (N > MAXN) N = MAXN;

    const int smem_bytes = (BR + 2 * BC) * SROW * 2 + 2 * BR * 4; // 169,472 B
    cudaFuncSetAttribute(sim_lse_kernel,
                         cudaFuncAttributeMaxDynamicSharedMemorySize, smem_bytes);

    norm_kernel<<<N, 256>>>(a, b);
    sim_lse_kernel<<<N / BR, 256, smem_bytes>>>(N);
    reduce_kernel<<<1, 256>>>((float*)d_out, N);
}

// round 3
// speedup vs baseline: 1.7712x; 1.7712x over previous
#include <cuda_runtime.h>
#include <cuda_bf16.h>
#include <cstdint>

#define D      256
#define MAXN   8192
#define BM     128                 // rows per CTA
#define BN     128                 // cols per tile
#define CSPLIT 2                   // column splits
#define NT     ((MAXN / CSPLIT) / BN)   // 32 tiles per CTA
#define LOG2E_OVER_T 28.853900817779268f
#define INV_T        20.0f

// SMEM layout (bytes)
#define SM_PART 0                  // 1024 B: 2 x 128 floats
#define SM_A    1024               // 128 rows x 512 B (swizzled)
#define SM_B0   (SM_A + 65536)
#define SM_B1   (SM_B0 + 65536)
#define SM_TOTAL (SM_B1 + 65536)   // 197632 B

// ---------------- scratch -------------------------------------------------
__device__ __align__(16) __nv_bfloat16 g_a[MAXN * D];
__device__ __align__(16) __nv_bfloat16 g_b[MAXN * D];
__device__ float g_diag[MAXN];
__device__ float g_part[MAXN * CSPLIT];

// ---------------- helpers --------------------------------------------------
__device__ __forceinline__ uint32_t smem_u32(const void* p) {
    return (uint32_t)__cvta_generic_to_shared(p);
}
__device__ __forceinline__ void cp_async16(uint32_t sdst, const void* gsrc) {
    asm volatile("cp.async.cg.shared.global [%0], [%1], 16;\n" :: "r"(sdst), "l"(gsrc));
}
#define CP_COMMIT() asm volatile("cp.async.commit_group;\n" ::: "memory")
#define CP_WAIT1()  asm volatile("cp.async.wait_group 1;\n" ::: "memory")

__device__ __forceinline__ float ex2f(float x) {
    float y; asm("ex2.approx.f32 %0, %1;" : "=f"(y) : "f"(x)); return y;
}
__device__ __forceinline__ void ldsm_x4(uint32_t r[4], uint32_t addr) {
    asm volatile("ldmatrix.sync.aligned.m8n8.x4.shared.b16 {%0,%1,%2,%3}, [%4];"
                 : "=r"(r[0]), "=r"(r[1]), "=r"(r[2]), "=r"(r[3]) : "r"(addr));
}
__device__ __forceinline__ void mma_bf16(float c[4], const uint32_t a[4],
                                         uint32_t b0, uint32_t b1) {
    asm volatile(
        "mma.sync.aligned.m16n8k16.row.col.f32.bf16.bf16.f32 "
        "{%0,%1,%2,%3}, {%4,%5,%6,%7}, {%8,%9}, {%0,%1,%2,%3};\n"
        : "+f"(c[0]), "+f"(c[1]), "+f"(c[2]), "+f"(c[3])
        : "r"(a[0]), "r"(a[1]), "r"(a[2]), "r"(a[3]), "r"(b0), "r"(b1));
}

// cp.async loader for a 128x256 bf16 tile, XOR-swizzled chunks (conflict-free LDSM)
__device__ __forceinline__ void load_tile(uint32_t sdst_base,
                                          const __nv_bfloat16* gsrc, int tid) {
    int c = tid & 31, r4 = tid >> 5;            // chunk 0..31, row group 0..3
    #pragma unroll
    for (int p = 0; p < 32; p++) {
        int row = p * 4 + r4;
        uint32_t sdst = sdst_base + row * 512 + (((uint32_t)(c ^ (row & 7))) << 4);
        cp_async16(sdst, gsrc + (size_t)row * D + c * 8);
    }
}

// ---------------- kernel 1: norms + exact diagonal (warp per row) ----------
__global__ void norm_kernel(const float4* __restrict__ a4, const float4* __restrict__ b4) {
    int w = threadIdx.x >> 5, lane = threadIdx.x & 31;
    int row = blockIdx.x * 8 + w;
    const float4* ar = a4 + (size_t)row * (D / 4);
    const float4* br = b4 + (size_t)row * (D / 4);
    float4 a0 = ar[lane * 2], a1 = ar[lane * 2 + 1];
    float4 b0 = br[lane * 2], b1 = br[lane * 2 + 1];

    float sa = a0.x*a0.x + a0.y*a0.y + a0.z*a0.z + a0.w*a0.w
             + a1.x*a1.x + a1.y*a1.y + a1.z*a1.z + a1.w*a1.w;
    float sb = b0.x*b0.x + b0.y*b0.y + b0.z*b0.z + b0.w*b0.w
             + b1.x*b1.x + b1.y*b1.y + b1.z*b1.z + b1.w*b1.w;
    float sd = a0.x*b0.x + a0.y*b0.y + a0.z*b0.z + a0.w*b0.w
             + a1.x*b1.x + a1.y*b1.y + a1.z*b1.z + a1.w*b1.w;
    #pragma unroll
    for (int o = 16; o; o >>= 1) {
        sa += __shfl_xor_sync(0xffffffffu, sa, o);
        sb += __shfl_xor_sync(0xffffffffu, sb, o);
        sd += __shfl_xor_sync(0xffffffffu, sd, o);
    }
    float ia = rsqrtf(fmaxf(sa, 1e-16f));
    float ib = rsqrtf(fmaxf(sb, 1e-16f));
    if (lane == 0) g_diag[row] = sd * ia * ib * INV_T;

    float fa = ia * LOG2E_OVER_T;
    __nv_bfloat162 p0 = __floats2bfloat162_rn(a0.x*fa, a0.y*fa);
    __nv_bfloat162 p1 = __floats2bfloat162_rn(a0.z*fa, a0.w*fa);
    __nv_bfloat162 p2 = __floats2bfloat162_rn(a1.x*fa, a1.y*fa);
    __nv_bfloat162 p3 = __floats2bfloat162_rn(a1.z*fa, a1.w*fa);
    uint4 ua = { *(uint32_t*)&p0, *(uint32_t*)&p1, *(uint32_t*)&p2, *(uint32_t*)&p3 };
    *(uint4*)(g_a + (size_t)row * D + lane * 8) = ua;

    __nv_bfloat162 q0 = __floats2bfloat162_rn(b0.x*ib, b0.y*ib);
    __nv_bfloat162 q1 = __floats2bfloat162_rn(b0.z*ib, b0.w*ib);
    __nv_bfloat162 q2 = __floats2bfloat162_rn(b1.x*ib, b1.y*ib);
    __nv_bfloat162 q3 = __floats2bfloat162_rn(b1.z*ib, b1.w*ib);
    uint4 ub = { *(uint32_t*)&q0, *(uint32_t*)&q1, *(uint32_t*)&q2, *(uint32_t*)&q3 };
    *(uint4*)(g_b + (size_t)row * D + lane * 8) = ub;
}

// ---------------- kernel 2: ldmatrix + mma GEMM + ex2 row-sum --------------
// 128 threads = 4 warps, 2x2 warp grid, 64x64 warp tile, CTA tile 128x128.
__global__ __launch_bounds__(128, 1) void sim_lse_kernel() {
    extern __shared__ char sm[];
    uint32_t sbase = smem_u32(sm);
    int tid = threadIdx.x, w = tid >> 5, lane = tid & 31;
    int rb = blockIdx.x >> 1, cs = blockIdx.x & 1;
    int rowBase = rb * BM;
    int col0 = cs * (MAXN / CSPLIT);

    int wr = (w & 1) * 64;        // warp row offset
    int wc = (w >> 1) * 64;       // warp col offset
    int g  = lane >> 3, l3 = lane & 7;
    uint32_t rk = (uint32_t)(l3 >> 1);       // XOR term for k-chunk (shared A/B)

    // ldmatrix base addresses (per m16 / n16 tile)
    uint32_t abase[4], boff[4];
    {
        uint32_t c0a = (uint32_t)(((g >> 1) ^ (l3 & 1)) << 4);
        uint32_t c0b = (uint32_t)(((g & 1) ^ (l3 & 1)) << 4);
        #pragma unroll
        for (int mt = 0; mt < 4; mt++) {
            int row = wr + mt * 16 + (g & 1) * 8 + l3;
            abase[mt] = sbase + SM_A + row * 512 + c0a;
        }
        #pragma unroll
        for (int nt = 0; nt < 4; nt++) {
            int n = wc + nt * 16 + (g >> 1) * 8 + l3;
            boff[nt] = (uint32_t)(n * 512) + c0b;      // add buffer base per tile
        }
    }

    // prologue: A tile + B tile 0 (group 0)
    load_tile(sbase + SM_A,  g_a + (size_t)rowBase * D, tid);
    load_tile(sbase + SM_B0, g_b + (size_t)col0 * D,   tid);
    CP_COMMIT();

    float acc[4][8][4];
    #pragma unroll
    for (int mt = 0; mt < 4; mt++)
        #pragma unroll
        for (int j = 0; j < 8; j++)
            acc[mt][j][0] = acc[mt][j][1] = acc[mt][j][2] = acc[mt][j][3] = 0.f;
    float rs0[4] = {0,0,0,0}, rs1[4] = {0,0,0,0};

    for (int t = 0; t < NT; t++) {
        __syncthreads();           // everyone done reading buf[(t+1)&1] (iter t-1)
        if (t + 1 < NT)
            load_tile(sbase + SM_B0 + ((t + 1) & 1) * 65536,
                      g_b + (size_t)(col0 + (t + 1) * BN) * D, tid);
        CP_COMMIT();               // empty group on last iter keeps wait_group 1 valid
        CP_WAIT1();                // group t retired -> buf[t&1] ready
        __syncthreads();

        uint32_t bbuf = sbase + SM_B0 + (t & 1) * 65536;

        #pragma unroll
        for (int kk = 0; kk < 16; kk++) {
            uint32_t koff = ((uint32_t)(kk ^ rk)) << 5;
            uint32_t af[4][4], bf[4][4];
            #pragma unroll
            for (int mt = 0; mt < 4; mt++) ldsm_x4(af[mt], abase[mt] + koff);
            #pragma unroll
            for (int nt = 0; nt < 4; nt++) ldsm_x4(bf[nt], bbuf + boff[nt] + koff);
            #pragma unroll
            for (int mt = 0; mt < 4; mt++) {
                #pragma unroll
                for (int nt = 0; nt < 4; nt++) {
                    mma_bf16(acc[mt][nt * 2],     af[mt], bf[nt][0], bf[nt][1]);
                    mma_bf16(acc[mt][nt * 2 + 1], af[mt], bf[nt][2], bf[nt][3]);
                }
            }
        }

        // epilogue: logits in log2 units, |x| <= 29 -> plain sum of 2^x
        #pragma unroll
        for (int mt = 0; mt < 4; mt++) {
            #pragma unroll
            for (int j = 0; j < 8; j++) {
                rs0[mt] += ex2f(acc[mt][j][0]) + ex2f(acc[mt][j][1]);
                rs1[mt] += ex2f(acc[mt][j][2]) + ex2f(acc[mt][j][3]);
                acc[mt][j][0] = acc[mt][j][1] = acc[mt][j][2] = acc[mt][j][3] = 0.f;
            }
        }
    }

    // reduce across the 4 lanes sharing each row (lane&3 spans cols)
    #pragma unroll
    for (int mt = 0; mt < 4; mt++) {
        rs0[mt] += __shfl_xor_sync(0xffffffffu, rs0[mt], 1);
        rs0[mt] += __shfl_xor_sync(0xffffffffu, rs0[mt], 2);
        rs1[mt] += __shfl_xor_sync(0xffffffffu, rs1[mt], 1);
        rs1[mt] += __shfl_xor_sync(0xffffffffu, rs1[mt], 2);
    }
    float* partial = (float*)(sm + SM_PART);
    if ((lane & 3) == 0) {
        int half = (w >> 1) * 128;
        #pragma unroll
        for (int mt = 0; mt < 4; mt++) {
            partial[half + wr + mt * 16 + (lane >> 2)]     = rs0[mt];
            partial[half + wr + mt * 16 + 8 + (lane >> 2)] = rs1[mt];
        }
    }
    __syncthreads();
    if (tid < 128)
        g_part[(size_t)(rowBase + tid) * CSPLIT + cs] = partial[tid] + partial[128 + tid];
}

// ---------------- kernel 3: final loss ------------------------------------
__global__ void reduce_kernel(float* __restrict__ out, int N) {
    __shared__ float s[256];
    int t = threadIdx.x;
    float acc = 0.f;
    for (int i = t; i < N; i += 256) {
        float sum2 = g_part[i * CSPLIT] + g_part[i * CSPLIT + 1];
        acc += __logf(sum2) - g_diag[i];       // log(sum 2^l2) = LSE (natural)
    }
    s[t] = acc;
    __syncthreads();
    for (int o = 128; o; o >>= 1) {
        if (t < o) s[t] += s[t + o];
        __syncthreads();
    }
    if (t == 0) out[0] = s[0] / (float)N;
}

// ---------------- launch ---------------------------------------------------
extern "C" void kernel_launch(void* const* d_in, const int* in_sizes, int n_in,
                              void* d_out, int out_size) {
    const float* a = (const float*)d_in[0];
    const float* b = (const float*)d_in[1];
    int N = in_sizes[0] / D;   // 8192

    cudaFuncSetAttribute(sim_lse_kernel,
                         cudaFuncAttributeMaxDynamicSharedMemorySize, SM_TOTAL);

    norm_kernel<<<N / 8, 256>>>((const float4*)a, (const float4*)b);
    sim_lse_kernel<<<(N / BM) * CSPLIT, 128, SM_TOTAL>>>();
    reduce_kernel<<<1, 256>>>((float*)d_out, N);
}